// round 7
// baseline (speedup 1.0000x reference)
#include <cuda_runtime.h>
#include <cstdint>

// Problem constants
#define BB   64
#define II   128
#define TT   1024
#define HH   256
#define G4   1024   // 4*H

// ---------------- scratch: pre-activations pre[b][t][4H] (256 MB) ----------
__device__ float g_pre[(size_t)BB * TT * G4];

// ---------------- helpers ----------------
__device__ __forceinline__ void ffma2(unsigned long long& d,
                                      unsigned long long a,
                                      unsigned long long b) {
    asm("fma.rn.f32x2 %0, %1, %2, %0;" : "+l"(d) : "l"(a), "l"(b));
}
__device__ __forceinline__ unsigned long long packf2(float a, float b) {
    unsigned long long r;
    asm("mov.b64 %0, {%1, %2};" : "=l"(r) : "f"(a), "f"(b));
    return r;
}
__device__ __forceinline__ float f2lo(unsigned long long v) {
    return __uint_as_float((unsigned)(v & 0xffffffffull));
}
__device__ __forceinline__ float f2hi(unsigned long long v) {
    return __uint_as_float((unsigned)(v >> 32));
}
__device__ __forceinline__ uint32_t mapa_rank(uint32_t addr, uint32_t r) {
    uint32_t out;
    asm("mapa.shared::cluster.u32 %0, %1, %2;" : "=r"(out) : "r"(addr), "r"(r));
    return out;
}
__device__ __forceinline__ void st_cluster_f32(uint32_t addr, float v) {
    asm volatile("st.shared::cluster.f32 [%0], %1;" :: "r"(addr), "f"(v) : "memory");
}
#define CLUSTER_SYNC() do { \
    asm volatile("barrier.cluster.arrive.aligned;" ::: "memory"); \
    asm volatile("barrier.cluster.wait.aligned;"   ::: "memory"); \
} while (0)

__device__ __forceinline__ float fast_sigmoid(float x) {
    return __frcp_rn(1.0f + __expf(-x));
}
__device__ __forceinline__ float fast_tanh(float x) {
    float ax = fabsf(x);
    float t  = __expf(-2.0f * ax);
    float r  = (1.0f - t) * __frcp_rn(1.0f + t);
    return copysignf(r, x);
}

// ============================================================================
// Phase 1: pre[b][t][g] = sum_i x[b,i,t] * W_ih[g,i] + b_ih[g] + b_hh[g]
// Tiling: CTA = (64 t) x (128 g), K=128 in 4 passes of 32. 256 threads,
// each thread computes 4t x 8g.
// ============================================================================
__global__ __launch_bounds__(256) void lstm_pre_kernel(
    const float* __restrict__ x,
    const float* __restrict__ W_ih,
    const float* __restrict__ b_ih,
    const float* __restrict__ b_hh)
{
    __shared__ __align__(16) float xs[32][68];    // [k][t]
    __shared__ __align__(16) float ws[32][132];   // [k][g]

    const int tid = threadIdx.x;
    const int tx  = tid & 15;    // g-group (8 g each)
    const int ty  = tid >> 4;    // t-group (4 t each)

    const int t0 = blockIdx.x * 64;
    const int g0 = blockIdx.y * 128;
    const int b  = blockIdx.z;

    const int gcol = g0 + tx * 8;

    float bias[8];
#pragma unroll
    for (int ig = 0; ig < 8; ig++)
        bias[ig] = b_ih[gcol + ig] + b_hh[gcol + ig];

    float acc[4][8];
#pragma unroll
    for (int it = 0; it < 4; it++)
#pragma unroll
        for (int ig = 0; ig < 8; ig++) acc[it][ig] = 0.0f;

    const size_t xbase = (size_t)b * II * TT;   // x[b, i, t] stride i = TT

    for (int kt = 0; kt < 4; kt++) {
        // load x tile [32 k][64 t]
#pragma unroll
        for (int idx = tid; idx < 32 * 64; idx += 256) {
            int k = idx >> 6, t = idx & 63;
            xs[k][t] = x[xbase + (size_t)(kt * 32 + k) * TT + t0 + t];
        }
        // load W tile transposed -> ws[k][g]
#pragma unroll
        for (int idx = tid; idx < 32 * 128; idx += 256) {
            int k = idx & 31, g = idx >> 5;
            ws[k][g] = W_ih[(size_t)(g0 + g) * II + kt * 32 + k];
        }
        __syncthreads();

#pragma unroll
        for (int k = 0; k < 32; k++) {
            float4 xv = *(const float4*)&xs[k][ty * 4];
            float4 wa = *(const float4*)&ws[k][tx * 8];
            float4 wb = *(const float4*)&ws[k][tx * 8 + 4];
            float xr[4] = {xv.x, xv.y, xv.z, xv.w};
            float wr[8] = {wa.x, wa.y, wa.z, wa.w, wb.x, wb.y, wb.z, wb.w};
#pragma unroll
            for (int it = 0; it < 4; it++)
#pragma unroll
                for (int ig = 0; ig < 8; ig++)
                    acc[it][ig] = fmaf(xr[it], wr[ig], acc[it][ig]);
        }
        __syncthreads();
    }

#pragma unroll
    for (int it = 0; it < 4; it++) {
        size_t orow = ((size_t)b * TT + (t0 + ty * 4 + it)) * G4 + gcol;
        float4 o1, o2;
        o1.x = acc[it][0] + bias[0]; o1.y = acc[it][1] + bias[1];
        o1.z = acc[it][2] + bias[2]; o1.w = acc[it][3] + bias[3];
        o2.x = acc[it][4] + bias[4]; o2.y = acc[it][5] + bias[5];
        o2.z = acc[it][6] + bias[6]; o2.w = acc[it][7] + bias[7];
        *(float4*)&g_pre[orow]     = o1;
        *(float4*)&g_pre[orow + 4] = o2;
    }
}

// ============================================================================
// Phase 2: recurrent LSTM scan.
// Cluster of 8 CTAs handles 4 batch elements. CTA rank r owns h-units
// [32r, 32r+32) => 128 gate rows, W_hh slice held in registers (f32x2 pairs).
// 512 threads: tid = row_local*4 + kpart, each thread does a 64-wide k-slice
// of one gate row for all 4 batches (FFMA2 packed over k-pairs).
// Pointwise (threads 0..127) updates c,h and pushes h to all 8 CTAs via DSMEM.
// ============================================================================
#define B_PER 4
#define HSEG  68                     // 64 + 4 pad (bank-conflict-free)
#define HBUF  (B_PER * 4 * HSEG)     // 1088 floats per buffer

__global__ void __cluster_dims__(8, 1, 1) __launch_bounds__(512, 1)
lstm_rec_kernel(const float* __restrict__ W_hh, float* __restrict__ out)
{
    __shared__ __align__(16) float h_s[2][HBUF];
    __shared__ __align__(16) float pre_s[2][B_PER * 128];
    __shared__ __align__(16) float gate_s[B_PER * 128];

    const int tid  = threadIdx.x;
    const int rl   = tid >> 2;         // row_local 0..127
    const int kp   = tid & 3;          // k-part 0..3
    const int unit = rl & 31;
    const int gate = rl >> 5;

    uint32_t rank;
    asm("mov.u32 %0, %%cluster_ctarank;" : "=r"(rank));
    const int clid = blockIdx.x >> 3;
    const int bg0  = clid * 4;         // first global batch of this cluster

    const int row_global = gate * HH + (int)rank * 32 + unit;

    // ---- load W_hh slice into registers as packed f32x2 pairs ----
    unsigned long long W2[32];
    {
        const float4* wrow =
            (const float4*)(W_hh + (size_t)row_global * HH + kp * 64);
#pragma unroll
        for (int j = 0; j < 16; j++) {
            float4 v = wrow[j];
            W2[2 * j]     = packf2(v.x, v.y);
            W2[2 * j + 1] = packf2(v.z, v.w);
        }
    }

    // ---- zero h buffer 0 ----
    for (int idx = tid; idx < HBUF; idx += 512) h_s[0][idx] = 0.0f;

    // ---- prefetch mapping (coalesced): pid=tid -> (b = tid>>7, rl = tid&127)
    const int  pb   = tid >> 7;
    const int  prl  = tid & 127;
    const int  prow = (prl >> 5) * HH + (int)rank * 32 + (prl & 31);
    const size_t pre_base = ((size_t)(bg0 + pb) * TT) * G4 + prow;

    // preload t=0
    pre_s[0][tid] = g_pre[pre_base];
    __syncthreads();
    CLUSTER_SYNC();

    // ---- pointwise thread state (threads 0..127) ----
    float c_reg = 0.0f;
    const int  pb2 = tid >> 5;                 // batch 0..3
    const int  pu  = tid & 31;                 // unit within rank
    const int  ug  = (int)rank * 32 + pu;      // global h unit
    const int  seg = ug >> 6;
    const int  wof = ug & 63;
    const size_t outbase =
        ((size_t)(bg0 + pb2) * HH + ug) * TT;  // out[b][ug][t]
    const int hofs_base = (pb2 * 4 + seg) * HSEG + wof;

    int cur = 0;
    for (int t = 0; t < TT; t++) {
        // prefetch next step's pre into a register (hidden under compute)
        float pre_next = 0.0f;
        if (t + 1 < TT) pre_next = g_pre[pre_base + (size_t)(t + 1) * G4];

        // ---- gate GEMV: 4 batches, FFMA2 over packed k-pairs ----
        float acc_keep = 0.0f;
#pragma unroll
        for (int b = 0; b < B_PER; b++) {
            const ulonglong2* hp = reinterpret_cast<const ulonglong2*>(
                &h_s[cur][(b * 4 + kp) * HSEG]);
            unsigned long long a0 = 0ull, a1 = 0ull;
#pragma unroll
            for (int j = 0; j < 16; j++) {
                ulonglong2 hv = hp[j];
                ffma2(a0, W2[2 * j],     hv.x);
                ffma2(a1, W2[2 * j + 1], hv.y);
            }
            float s = (f2lo(a0) + f2hi(a0)) + (f2lo(a1) + f2hi(a1));
            s += __shfl_xor_sync(0xffffffffu, s, 1);
            s += __shfl_xor_sync(0xffffffffu, s, 2);
            if (kp == b) acc_keep = s;
        }
        // this thread is responsible for batch b == kp
        gate_s[kp * 128 + rl] = acc_keep + pre_s[cur][kp * 128 + rl];
        pre_s[cur ^ 1][tid] = pre_next;
        __syncthreads();

        // ---- pointwise LSTM cell + h broadcast ----
        if (tid < 128) {
            float gi = gate_s[pb2 * 128 +  0 + pu];
            float gf = gate_s[pb2 * 128 + 32 + pu];
            float gg = gate_s[pb2 * 128 + 64 + pu];
            float go = gate_s[pb2 * 128 + 96 + pu];
            float i = fast_sigmoid(gi);
            float f = fast_sigmoid(gf);
            float g = fast_tanh(gg);
            float o = fast_sigmoid(go);
            c_reg = fmaf(f, c_reg, i * g);
            float h = o * fast_tanh(c_reg);
            out[outbase + t] = fmaxf(h, 0.0f);

            uint32_t laddr = (uint32_t)__cvta_generic_to_shared(
                &h_s[cur ^ 1][hofs_base]);
#pragma unroll
            for (uint32_t r = 0; r < 8; r++)
                st_cluster_f32(mapa_rank(laddr, r), h);
        }
        CLUSTER_SYNC();
        cur ^= 1;
    }
}

// ============================================================================
extern "C" void kernel_launch(void* const* d_in, const int* in_sizes, int n_in,
                              void* d_out, int out_size)
{
    const float* x    = (const float*)d_in[0];
    const float* W_ih = (const float*)d_in[1];
    const float* W_hh = (const float*)d_in[2];
    const float* b_ih = (const float*)d_in[3];
    const float* b_hh = (const float*)d_in[4];
    float* out = (float*)d_out;

    dim3 g1(TT / 64, G4 / 128, BB);   // 16 x 8 x 64
    lstm_pre_kernel<<<g1, 256>>>(x, W_ih, b_ih, b_hh);

    lstm_rec_kernel<<<128, 512>>>(W_hh, out);   // 16 clusters of 8 CTAs
}

// round 9
// speedup vs baseline: 1.5000x; 1.5000x over previous
#include <cuda_runtime.h>
#include <cstdint>

// Problem constants
#define BB   64
#define II   128
#define TT   1024
#define HH   256
#define G4   1024   // 4*H

// ---------------- scratch: pre-activations pre[b][t][4H] (256 MB) ----------
__device__ float g_pre[(size_t)BB * TT * G4];

// ---------------- helpers ----------------
__device__ __forceinline__ void ffma2(unsigned long long& d,
                                      unsigned long long a,
                                      unsigned long long b) {
    asm("fma.rn.f32x2 %0, %1, %2, %0;" : "+l"(d) : "l"(a), "l"(b));
}
__device__ __forceinline__ unsigned long long packf2(float a, float b) {
    unsigned long long r;
    asm("mov.b64 %0, {%1, %2};" : "=l"(r) : "f"(a), "f"(b));
    return r;
}
__device__ __forceinline__ float f2lo(unsigned long long v) {
    return __uint_as_float((unsigned)(v & 0xffffffffull));
}
__device__ __forceinline__ float f2hi(unsigned long long v) {
    return __uint_as_float((unsigned)(v >> 32));
}
__device__ __forceinline__ uint32_t mapa_rank(uint32_t addr, uint32_t r) {
    uint32_t out;
    asm("mapa.shared::cluster.u32 %0, %1, %2;" : "=r"(out) : "r"(addr), "r"(r));
    return out;
}
#define CLUSTER_SYNC() do { \
    asm volatile("barrier.cluster.arrive.aligned;" ::: "memory"); \
    asm volatile("barrier.cluster.wait.aligned;"   ::: "memory"); \
} while (0)

#define MBAR_INIT(addr, cnt) \
    asm volatile("mbarrier.init.shared.b64 [%0], %1;" :: "r"(addr), "r"(cnt) : "memory")
#define MBAR_EXPECT_TX(addr, bytes) \
    asm volatile("mbarrier.arrive.expect_tx.shared.b64 _, [%0], %1;" \
                 :: "r"(addr), "r"(bytes) : "memory")

__device__ __forceinline__ void mbar_wait_acq(uint32_t mbar, uint32_t parity) {
    asm volatile(
        "{\n\t"
        ".reg .pred P;\n\t"
        "MWL_%=:\n\t"
        "mbarrier.try_wait.parity.acquire.cluster.shared::cta.b64 P, [%0], %1, 0x989680;\n\t"
        "@!P bra MWL_%=;\n\t"
        "}"
        :: "r"(mbar), "r"(parity) : "memory");
}

__device__ __forceinline__ void st_async_f32(uint32_t raddr, float v, uint32_t rmbar) {
    asm volatile(
        "st.async.weak.shared::cluster.mbarrier::complete_tx::bytes.b32 [%0], %1, [%2];"
        :: "r"(raddr), "r"(__float_as_uint(v)), "r"(rmbar) : "memory");
}

// ============================================================================
// Phase 1: pre[b][t][g] = sum_i x[b,i,t] * W_ih[g,i] + b_ih[g] + b_hh[g]
// CTA = 64t x 128g, 256 threads; FFMA2 over gate-pairs (w-pairs from float4).
// ============================================================================
__global__ __launch_bounds__(256) void lstm_pre_kernel(
    const float* __restrict__ x,
    const float* __restrict__ W_ih,
    const float* __restrict__ b_ih,
    const float* __restrict__ b_hh)
{
    __shared__ __align__(16) float xs[32][68];    // [k][t]
    __shared__ __align__(16) float ws[32][136];   // [k][g], rows 16B-aligned

    const int tid = threadIdx.x;
    const int tx  = tid & 15;    // g-group (8 g each)
    const int ty  = tid >> 4;    // t-group (4 t each)

    const int t0 = blockIdx.x * 64;
    const int g0 = blockIdx.y * 128;
    const int b  = blockIdx.z;

    const int gcol = g0 + tx * 8;

    float bias[8];
#pragma unroll
    for (int ig = 0; ig < 8; ig++)
        bias[ig] = b_ih[gcol + ig] + b_hh[gcol + ig];

    unsigned long long acc[4][4];   // [t][gpair] lanes = (g even, g odd)
#pragma unroll
    for (int it = 0; it < 4; it++)
#pragma unroll
        for (int gpi = 0; gpi < 4; gpi++) acc[it][gpi] = 0ull;

    const size_t xbase = (size_t)b * II * TT;   // x[b, i, t] stride i = TT

    for (int kt = 0; kt < 4; kt++) {
#pragma unroll
        for (int idx = tid; idx < 32 * 64; idx += 256) {
            int k = idx >> 6, t = idx & 63;
            xs[k][t] = x[xbase + (size_t)(kt * 32 + k) * TT + t0 + t];
        }
#pragma unroll
        for (int idx = tid; idx < 32 * 128; idx += 256) {
            int k = idx & 31, g = idx >> 5;
            ws[k][g] = W_ih[(size_t)(g0 + g) * II + kt * 32 + k];
        }
        __syncthreads();

#pragma unroll
        for (int k = 0; k < 32; k++) {
            float4 xv = *(const float4*)&xs[k][ty * 4];
            ulonglong2 wA = *(const ulonglong2*)&ws[k][tx * 8];      // (g0,g1),(g2,g3)
            ulonglong2 wB = *(const ulonglong2*)&ws[k][tx * 8 + 4];  // (g4,g5),(g6,g7)
            float xr[4] = {xv.x, xv.y, xv.z, xv.w};
#pragma unroll
            for (int it = 0; it < 4; it++) {
                unsigned long long xx = packf2(xr[it], xr[it]);
                ffma2(acc[it][0], wA.x, xx);
                ffma2(acc[it][1], wA.y, xx);
                ffma2(acc[it][2], wB.x, xx);
                ffma2(acc[it][3], wB.y, xx);
            }
        }
        __syncthreads();
    }

#pragma unroll
    for (int it = 0; it < 4; it++) {
        size_t orow = ((size_t)b * TT + (t0 + ty * 4 + it)) * G4 + gcol;
        float4 o1, o2;
        o1.x = f2lo(acc[it][0]) + bias[0]; o1.y = f2hi(acc[it][0]) + bias[1];
        o1.z = f2lo(acc[it][1]) + bias[2]; o1.w = f2hi(acc[it][1]) + bias[3];
        o2.x = f2lo(acc[it][2]) + bias[4]; o2.y = f2hi(acc[it][2]) + bias[5];
        o2.z = f2lo(acc[it][3]) + bias[6]; o2.w = f2hi(acc[it][3]) + bias[7];
        *(float4*)&g_pre[orow]     = o1;
        *(float4*)&g_pre[orow + 4] = o2;
    }
}

// ============================================================================
// Phase 2: recurrent scan. Cluster of 8 CTAs = 4 batches; CTA rank owns units
// [32r,32r+32). Thread (u, gp, kp) holds 2 gate rows x 32-k slice in regs.
// Partials (2 gates x 4 batches) reduce-scatter over the 8 kp lanes (7 shfls),
// distributed activations (1 exp+rcp per lane), 3-shfl gather to i-lane.
// h exchanged via st.async + double-buffered mbarrier (expect_tx 4096B).
// Zero block/cluster barriers inside the loop.
// ============================================================================
#define BSLAB  288                  // floats per batch slab: 8 slices * 36 (padded)
#define HBUFSZ (4 * BSLAB)          // 1152 floats per buffer
#define TXBYTES 4096                // 1024 h floats per CTA per step

__global__ void __cluster_dims__(8, 1, 1) __launch_bounds__(512)
lstm_rec_kernel(const float* __restrict__ W_hh, float* __restrict__ out)
{
    __shared__ __align__(16) float h_s[2][HBUFSZ];
    __shared__ __align__(8) unsigned long long mbar[2];

    const int tid = threadIdx.x;
    const int kp  = tid & 7;          // k-slice 0..7 (32 k each)
    const int gp  = (tid >> 3) & 1;   // gate-pair: 0 -> (i,f), 1 -> (g,o)
    const int u   = tid >> 4;         // unit 0..31 within rank

    uint32_t rank;
    asm("mov.u32 %0, %%cluster_ctarank;" : "=r"(rank));
    const int clid = blockIdx.x >> 3;
    const int bg0  = clid * 4;
    const int ug   = (int)rank * 32 + u;

    // ---- W_hh: rows (gp*2, gp*2+1), k-slice [kp*32, +32), as f32x2 pairs ----
    unsigned long long W2[2][16];
#pragma unroll
    for (int g = 0; g < 2; g++) {
        const int row = (gp * 2 + g) * HH + ug;
        const float4* wr = (const float4*)(W_hh + (size_t)row * HH + kp * 32);
#pragma unroll
        for (int j = 0; j < 8; j++) {
            float4 v = wr[j];
            W2[g][2 * j]     = packf2(v.x, v.y);
            W2[g][2 * j + 1] = packf2(v.z, v.w);
        }
    }

    // zero buffer 0 (read at t=0)
    for (int i = tid; i < HBUFSZ; i += 512) h_s[0][i] = 0.0f;

    const uint32_t hs_addr = (uint32_t)__cvta_generic_to_shared(&h_s[0][0]);
    const uint32_t mb_addr = (uint32_t)__cvta_generic_to_shared(&mbar[0]);

    if (tid == 0) {
        MBAR_INIT(mb_addr, 1);
        MBAR_INIT(mb_addr + 8, 1);
        MBAR_EXPECT_TX(mb_addr, TXBYTES);        // first waited at t=2
        MBAR_EXPECT_TX(mb_addr + 8, TXBYTES);    // first waited at t=1
    }
    __syncthreads();
    CLUSTER_SYNC();   // all peers zeroed + armed before any st.async flies

    // lane (gp,kp) owns gate = gp*2 + (kp>>2), batch = kp&3 after reduce
    const int gate_lane = gp * 2 + (kp >> 2);
    const int b_lane    = kp & 3;
    const float* pp = g_pre + ((size_t)(bg0 + b_lane) * TT) * G4
                            + gate_lane * HH + ug;
    float pre_next = pp[0];

    const bool ilane = (gp == 0) && (kp < 4);     // owns cell (u, b=kp)
    float c_reg = 0.0f;
    const size_t outbase = ((size_t)(bg0 + kp) * HH + ug) * TT;
    // h value for unit ug lands at slab b + slice (ug>>5)=rank + (ug&31)=u
    const uint32_t hoff = (uint32_t)((kp * BSLAB + (int)rank * 36 + u) * 4);
    const uint32_t dmb  = mb_addr - hs_addr;      // wrap-safe offset

    uint32_t rb[8];
#pragma unroll
    for (uint32_t r = 0; r < 8; r++) rb[r] = mapa_rank(hs_addr, r);

    uint32_t par0 = 0, par1 = 0;

    for (int t = 0; t < TT; t++) {
        // ---- wait for this step's h (all 4096 bytes landed); re-arm ----
        if (t > 0) {
            if (t & 1) {
                mbar_wait_acq(mb_addr + 8, par1); par1 ^= 1;
                if (tid == 0) MBAR_EXPECT_TX(mb_addr + 8, TXBYTES);
            } else {
                mbar_wait_acq(mb_addr, par0); par0 ^= 1;
                if (tid == 0) MBAR_EXPECT_TX(mb_addr, TXBYTES);
            }
        }
        const float pre_cur = pre_next;
        pre_next = (t + 1 < TT) ? pp[(size_t)(t + 1) * G4] : 0.0f;  // ~1 step early

        // ---- GEMV: 2 gates x 4 batches over 32-k slice (8 LDS.128 / batch) ----
        const float* hb = &h_s[t & 1][kp * 36];
        float A[2][4];
#pragma unroll
        for (int b = 0; b < 4; b++) {
            const ulonglong2* hv = (const ulonglong2*)(hb + b * BSLAB);
            unsigned long long a00 = 0ull, a01 = 0ull, a10 = 0ull, a11 = 0ull;
#pragma unroll
            for (int j = 0; j < 8; j++) {
                ulonglong2 h2 = hv[j];
                ffma2(a00, W2[0][2 * j],     h2.x);
                ffma2(a01, W2[0][2 * j + 1], h2.y);
                ffma2(a10, W2[1][2 * j],     h2.x);
                ffma2(a11, W2[1][2 * j + 1], h2.y);
            }
            A[0][b] = (f2lo(a00) + f2hi(a00)) + (f2lo(a01) + f2hi(a01));
            A[1][b] = (f2lo(a10) + f2hi(a10)) + (f2lo(a11) + f2hi(a11));
        }

        // ---- reduce-scatter over 8 kp lanes: 7 shfls ----
        const int sel = kp >> 2;
        float B0[4];
#pragma unroll
        for (int b = 0; b < 4; b++) {
            float sendv = sel ? A[0][b] : A[1][b];
            float keepv = sel ? A[1][b] : A[0][b];
            B0[b] = keepv + __shfl_xor_sync(0xffffffffu, sendv, 4);
        }
        const int t1 = (kp >> 1) & 1;
        {
            float s0 = t1 ? B0[0] : B0[2];
            float s1 = t1 ? B0[1] : B0[3];
            float k0 = t1 ? B0[2] : B0[0];
            float k1 = t1 ? B0[3] : B0[1];
            B0[0] = k0 + __shfl_xor_sync(0xffffffffu, s0, 2);
            B0[1] = k1 + __shfl_xor_sync(0xffffffffu, s1, 2);
        }
        const int tb0 = kp & 1;
        float sendv = tb0 ? B0[0] : B0[1];
        float keepv = tb0 ? B0[1] : B0[0];
        float gv = keepv + __shfl_xor_sync(0xffffffffu, sendv, 1) + pre_cur;

        // ---- distributed activation: sigmoid, or tanh = 2*sigmoid(2x)-1 ----
        const bool isg = (gate_lane == 2);
        float sarg = isg ? 2.0f * gv : gv;
        float e = __expf(-sarg);
        float y = __frcp_rn(1.0f + e);
        float act = isg ? fmaf(2.0f, y, -1.0f) : y;

        // gather f,g,o to the i-lane (all lanes execute shfls)
        float fv = __shfl_xor_sync(0xffffffffu, act, 4);
        float gg = __shfl_xor_sync(0xffffffffu, act, 8);
        float ov = __shfl_xor_sync(0xffffffffu, act, 12);

        if (ilane) {
            c_reg = fmaf(fv, c_reg, act * gg);
            float ax  = fabsf(c_reg);
            float tt2 = __expf(-2.0f * ax);
            float th  = (1.0f - tt2) * __frcp_rn(1.0f + tt2);
            th = copysignf(th, c_reg);
            float h = ov * th;
            out[outbase + t] = fmaxf(h, 0.0f);

            if (t + 1 < TT) {
                const uint32_t boff = hoff + (((t + 1) & 1) ? (uint32_t)(HBUFSZ * 4) : 0u);
                const uint32_t moff = dmb + (uint32_t)(((t + 1) & 1) << 3);
#pragma unroll
                for (int r = 0; r < 8; r++)
                    st_async_f32(rb[r] + boff, h, rb[r] + moff);
            }
        }
    }
    CLUSTER_SYNC();   // no CTA exits while peers' smem may still receive traffic
}

// ============================================================================
extern "C" void kernel_launch(void* const* d_in, const int* in_sizes, int n_in,
                              void* d_out, int out_size)
{
    const float* x    = (const float*)d_in[0];
    const float* W_ih = (const float*)d_in[1];
    const float* W_hh = (const float*)d_in[2];
    const float* b_ih = (const float*)d_in[3];
    const float* b_hh = (const float*)d_in[4];
    float* out = (float*)d_out;

    dim3 g1(TT / 64, G4 / 128, BB);   // 16 x 8 x 64
    lstm_pre_kernel<<<g1, 256>>>(x, W_ih, b_ih, b_hh);

    lstm_rec_kernel<<<128, 512>>>(W_hh, out);   // 16 clusters of 8 CTAs
}